// round 2
// baseline (speedup 1.0000x reference)
#include <cuda_runtime.h>
#include <math.h>

// Problem constants
#define EN      200000
#define IND     128
#define HIDD    32
#define NH      4
#define OUTD    128
#define MAXK    16
#define TM      64          // rows per block
#define NBLK    (EN / TM)   // 3125

// Scratch (device globals; no allocation)
__device__ float g_kv[(size_t)EN * 256];   // [e][0:128]=k (head-major), [128:256]=v
__device__ float g_bh[(size_t)EN * NH];    // [e][h]
__device__ float g_x [(size_t)EN * 128];   // gated attention output (concat heads)
__device__ int   g_kstride;                // 2 if klist is int64, 1 if int32

// ---------------------------------------------------------------------------
// Prologue: detect klist element width. int64 data viewed as int32 pairs has
// every odd word == 0 or -1 (sign extension of indices in [0,E) or -1).
// ---------------------------------------------------------------------------
__global__ void kdetect(const int* __restrict__ kw)
{
    if (threadIdx.x == 0 && blockIdx.x == 0) {
        int is64 = 1;
        for (int i = 0; i < 4096; i++) {
            int hi = kw[2 * i + 1];
            if (hi != 0 && hi != -1) { is64 = 0; break; }
        }
        g_kstride = is64 ? 2 : 1;
    }
}

// ---------------------------------------------------------------------------
// Kernel A: KV + b projection.  C[64 x 256] = Ztile[64x128] @ [Wk;Wv]^T,
// plus 4 b columns. Tiled smem SGEMM, 256 threads, 4x4 register tiles.
// ---------------------------------------------------------------------------
__global__ void __launch_bounds__(256, 1) kproj_kv(
    const float* __restrict__ Z,
    const float* __restrict__ Wk,
    const float* __restrict__ Wv,
    const float* __restrict__ Wb)
{
    extern __shared__ float sm[];
    float* sZt = sm;                  // [128][68]  (k, row)
    float* sW  = sm + 128 * 68;       // [128][68]  (k, col-in-chunk)
    float* sWb = sm + 2 * 128 * 68;   // [512]

    const int tid  = threadIdx.x;
    const int row0 = blockIdx.x * TM;

    // Load Z tile transposed into smem
    const float4* Z4 = (const float4*)(Z + (size_t)row0 * IND);
    for (int i = tid; i < TM * 32; i += 256) {
        int r = i >> 5, c = i & 31;
        float4 v = Z4[r * 32 + c];
        sZt[(c * 4 + 0) * 68 + r] = v.x;
        sZt[(c * 4 + 1) * 68 + r] = v.y;
        sZt[(c * 4 + 2) * 68 + r] = v.z;
        sZt[(c * 4 + 3) * 68 + r] = v.w;
    }
    for (int i = tid; i < NH * IND; i += 256) sWb[i] = Wb[i];

    const int ty = tid >> 4, tx = tid & 15;

    for (int chunk = 0; chunk < 4; chunk++) {
        __syncthreads();   // sW reuse barrier (also covers sZt on first iter)
        for (int i = tid; i < 64 * 32; i += 256) {
            int c = i >> 5, kq = i & 31;
            int col = chunk * 64 + c;
            const float* wrow = (col < 128) ? (Wk + (size_t)col * IND)
                                            : (Wv + (size_t)(col - 128) * IND);
            float4 w = *(const float4*)(wrow + kq * 4);
            sW[(kq * 4 + 0) * 68 + c] = w.x;
            sW[(kq * 4 + 1) * 68 + c] = w.y;
            sW[(kq * 4 + 2) * 68 + c] = w.z;
            sW[(kq * 4 + 3) * 68 + c] = w.w;
        }
        __syncthreads();

        float acc[4][4] = {};
        #pragma unroll 8
        for (int k = 0; k < 128; k++) {
            float4 a = *(const float4*)(sZt + k * 68 + ty * 4);
            float4 b = *(const float4*)(sW  + k * 68 + tx * 4);
            float av[4] = {a.x, a.y, a.z, a.w};
            float bv[4] = {b.x, b.y, b.z, b.w};
            #pragma unroll
            for (int i = 0; i < 4; i++)
                #pragma unroll
                for (int j = 0; j < 4; j++)
                    acc[i][j] += av[i] * bv[j];
        }
        #pragma unroll
        for (int i = 0; i < 4; i++) {
            float4 o = make_float4(acc[i][0], acc[i][1], acc[i][2], acc[i][3]);
            *(float4*)&g_kv[(size_t)(row0 + ty * 4 + i) * 256 + chunk * 64 + tx * 4] = o;
        }
    }

    // b tail: one dot per (row, head)
    const int r = tid >> 2, h = tid & 3;
    float s = 0.f;
    #pragma unroll 8
    for (int k = 0; k < 128; k++) s += sZt[k * 68 + r] * sWb[h * IND + k];
    g_bh[(size_t)(row0 + r) * NH + h] = s;
}

// ---------------------------------------------------------------------------
// Kernel B: fused q/g projection + gather attention + gating -> g_x
// ---------------------------------------------------------------------------
__global__ void __launch_bounds__(256, 1) katt(
    const float* __restrict__ Z,
    const float* __restrict__ Wq,
    const float* __restrict__ Wg,
    const float* __restrict__ bg,
    const int*   __restrict__ kw)   // klist as raw int32 words
{
    extern __shared__ float sm[];
    float* sZt = sm;                          // [128][68]
    float* sW  = sZt + 128 * 68;              // [128][68]
    float* sQ  = sW  + 128 * 68;              // [64][136]
    float* sG  = sQ  + 64 * 136;              // [64][136]
    int*   skl = (int*)(sG + 64 * 136);       // [64][32]

    const int tid  = threadIdx.x;
    const int row0 = blockIdx.x * TM;
    const int st   = g_kstride;               // 2 for int64, 1 for int32

    // Load Z tile transposed
    const float4* Z4 = (const float4*)(Z + (size_t)row0 * IND);
    for (int i = tid; i < TM * 32; i += 256) {
        int r = i >> 5, c = i & 31;
        float4 v = Z4[r * 32 + c];
        sZt[(c * 4 + 0) * 68 + r] = v.x;
        sZt[(c * 4 + 1) * 68 + r] = v.y;
        sZt[(c * 4 + 2) * 68 + r] = v.z;
        sZt[(c * 4 + 3) * 68 + r] = v.w;
    }
    // Load klist words: per-row layout [ii(16) | jj(16)]
    for (int i = tid; i < TM * 32; i += 256)
        skl[i] = kw[((size_t)row0 * 32 + i) * st];

    const int ty = tid >> 4, tx = tid & 15;

    // Phase 1: q (cols 0..127) and g (cols 128..255)
    for (int chunk = 0; chunk < 4; chunk++) {
        __syncthreads();
        for (int i = tid; i < 64 * 32; i += 256) {
            int c = i >> 5, kq = i & 31;
            int col = chunk * 64 + c;
            const float* wrow = (col < 128) ? (Wq + (size_t)col * IND)
                                            : (Wg + (size_t)(col - 128) * IND);
            float4 w = *(const float4*)(wrow + kq * 4);
            sW[(kq * 4 + 0) * 68 + c] = w.x;
            sW[(kq * 4 + 1) * 68 + c] = w.y;
            sW[(kq * 4 + 2) * 68 + c] = w.z;
            sW[(kq * 4 + 3) * 68 + c] = w.w;
        }
        __syncthreads();

        float acc[4][4] = {};
        #pragma unroll 8
        for (int k = 0; k < 128; k++) {
            float4 a = *(const float4*)(sZt + k * 68 + ty * 4);
            float4 b = *(const float4*)(sW  + k * 68 + tx * 4);
            float av[4] = {a.x, a.y, a.z, a.w};
            float bv[4] = {b.x, b.y, b.z, b.w};
            #pragma unroll
            for (int i = 0; i < 4; i++)
                #pragma unroll
                for (int j = 0; j < 4; j++)
                    acc[i][j] += av[i] * bv[j];
        }
        #pragma unroll
        for (int i = 0; i < 4; i++) {
            int r = ty * 4 + i;
            #pragma unroll
            for (int j = 0; j < 4; j++) {
                int col = chunk * 64 + tx * 4 + j;
                if (col < 128) {
                    sQ[r * 136 + col] = acc[i][j];
                } else {
                    float x = acc[i][j] + bg[col - 128];
                    sG[r * 136 + (col - 128)] = 1.f / (1.f + expf(-x));
                }
            }
        }
    }
    __syncthreads();

    // Phase 2: one thread per (row, head)
    const int r = tid >> 2, h = tid & 3;
    const size_t e = (size_t)row0 + r;

    float q[32];
    #pragma unroll
    for (int c = 0; c < 8; c++) {
        float4 t = *(const float4*)&sQ[r * 136 + h * 32 + c * 4];
        q[c * 4 + 0] = t.x; q[c * 4 + 1] = t.y; q[c * 4 + 2] = t.z; q[c * 4 + 3] = t.w;
    }

    const float scale = 0.17677669529663687f;   // 1/sqrt(32)
    float sc[MAXK];
    float m = -1e30f;
    #pragma unroll 4
    for (int s = 0; s < MAXK; s++) {
        int ii = skl[r * 32 + s];
        float v = 0.f;
        if (ii >= 0) {
            ii = min(ii, EN - 1);                       // defensive clamp
            const float4* kp = (const float4*)&g_kv[(size_t)ii * 256 + h * 32];
            float d = 0.f;
            #pragma unroll
            for (int c = 0; c < 8; c++) {
                float4 kk = kp[c];
                d += q[c*4+0]*kk.x + q[c*4+1]*kk.y + q[c*4+2]*kk.z + q[c*4+3]*kk.w;
            }
            int jj = skl[r * 32 + 16 + s];
            jj = min(max(jj, 0), EN - 1);               // defensive clamp
            v = scale * d + g_bh[(size_t)jj * NH + h];
        }
        sc[s] = v;
        m = fmaxf(m, v);
    }

    float den = 0.f;
    #pragma unroll
    for (int s = 0; s < MAXK; s++) {
        float ex = expf(sc[s] - m);
        sc[s] = ex;
        den += ex;
    }

    float att[32];
    #pragma unroll
    for (int j = 0; j < 32; j++) att[j] = 0.f;

    #pragma unroll 4
    for (int s = 0; s < MAXK; s++) {
        int ii = skl[r * 32 + s];
        if (ii >= 0) {
            ii = min(ii, EN - 1);                       // defensive clamp
            const float4* vp = (const float4*)&g_kv[(size_t)ii * 256 + 128 + h * 32];
            float w = sc[s];
            #pragma unroll
            for (int c = 0; c < 8; c++) {
                float4 vv = vp[c];
                att[c*4+0] += w * vv.x; att[c*4+1] += w * vv.y;
                att[c*4+2] += w * vv.z; att[c*4+3] += w * vv.w;
            }
        }
    }

    const float inv = 1.f / den;
    #pragma unroll
    for (int c = 0; c < 8; c++) {
        float4 g4 = *(const float4*)&sG[r * 136 + h * 32 + c * 4];
        float4 o;
        o.x = g4.x * att[c*4+0] * inv;
        o.y = g4.y * att[c*4+1] * inv;
        o.z = g4.z * att[c*4+2] * inv;
        o.w = g4.w * att[c*4+3] * inv;
        *(float4*)&g_x[e * 128 + h * 32 + c * 4] = o;
    }
}

// ---------------------------------------------------------------------------
// Kernel C: out = X @ Wout^T + bout   (64-row x 128-col tiles)
// ---------------------------------------------------------------------------
__global__ void __launch_bounds__(256, 1) kout(
    const float* __restrict__ Wout,
    const float* __restrict__ bout,
    float* __restrict__ out)
{
    extern __shared__ float sm[];
    float* sXt = sm;              // [128][68]  (k, row)
    float* sWt = sm + 128 * 68;   // [128][132] (k, out-col)

    const int tid  = threadIdx.x;
    const int row0 = blockIdx.x * TM;

    const float4* X4 = (const float4*)(g_x + (size_t)row0 * 128);
    for (int i = tid; i < TM * 32; i += 256) {
        int r = i >> 5, c = i & 31;
        float4 v = X4[r * 32 + c];
        sXt[(c * 4 + 0) * 68 + r] = v.x;
        sXt[(c * 4 + 1) * 68 + r] = v.y;
        sXt[(c * 4 + 2) * 68 + r] = v.z;
        sXt[(c * 4 + 3) * 68 + r] = v.w;
    }
    const float4* W4 = (const float4*)Wout;
    for (int i = tid; i < 128 * 32; i += 256) {
        int o = i >> 5, kq = i & 31;
        float4 w = W4[o * 32 + kq];
        sWt[(kq * 4 + 0) * 132 + o] = w.x;
        sWt[(kq * 4 + 1) * 132 + o] = w.y;
        sWt[(kq * 4 + 2) * 132 + o] = w.z;
        sWt[(kq * 4 + 3) * 132 + o] = w.w;
    }
    __syncthreads();

    const int ty = tid >> 4, tx = tid & 15;   // rows ty*4.., cols tx*8..
    float acc[4][8] = {};
    #pragma unroll 4
    for (int k = 0; k < 128; k++) {
        float4 a  = *(const float4*)(sXt + k * 68 + ty * 4);
        float4 b0 = *(const float4*)(sWt + k * 132 + tx * 8);
        float4 b1 = *(const float4*)(sWt + k * 132 + tx * 8 + 4);
        float av[4] = {a.x, a.y, a.z, a.w};
        float bv[8] = {b0.x, b0.y, b0.z, b0.w, b1.x, b1.y, b1.z, b1.w};
        #pragma unroll
        for (int i = 0; i < 4; i++)
            #pragma unroll
            for (int j = 0; j < 8; j++)
                acc[i][j] += av[i] * bv[j];
    }

    float bb[8];
    #pragma unroll
    for (int j = 0; j < 8; j++) bb[j] = bout[tx * 8 + j];

    #pragma unroll
    for (int i = 0; i < 4; i++) {
        size_t e = (size_t)(row0 + ty * 4 + i);
        float4 o0 = make_float4(acc[i][0] + bb[0], acc[i][1] + bb[1],
                                acc[i][2] + bb[2], acc[i][3] + bb[3]);
        float4 o1 = make_float4(acc[i][4] + bb[4], acc[i][5] + bb[5],
                                acc[i][6] + bb[6], acc[i][7] + bb[7]);
        *(float4*)&out[e * 128 + tx * 8]     = o0;
        *(float4*)&out[e * 128 + tx * 8 + 4] = o1;
    }
}

// ---------------------------------------------------------------------------
extern "C" void kernel_launch(void* const* d_in, const int* in_sizes, int n_in,
                              void* d_out, int out_size)
{
    // Locate Z and klist by element count; remaining inputs keep dict order:
    // Wq, Wk, Wv, Wb, Wg, bg, Wout, bout
    const float* Z = nullptr;
    const int*   klist = nullptr;
    const void*  rest[16];
    int nrest = 0;
    for (int i = 0; i < n_in; i++) {
        if (in_sizes[i] == 25600000)      Z     = (const float*)d_in[i];
        else if (in_sizes[i] == 6400000)  klist = (const int*)d_in[i];
        else                              rest[nrest++] = d_in[i];
    }
    const float* Wq   = (const float*)rest[0];
    const float* Wk   = (const float*)rest[1];
    const float* Wv   = (const float*)rest[2];
    const float* Wb   = (const float*)rest[3];
    const float* Wg   = (const float*)rest[4];
    const float* bg   = (const float*)rest[5];
    const float* Wout = (const float*)rest[6];
    const float* bout = (const float*)rest[7];
    float* out = (float*)d_out;

    const int smemA = (2 * 128 * 68 + 512) * 4;                        // 71,680 B
    const int smemB = (2 * 128 * 68 + 2 * 64 * 136) * 4 + TM * 32 * 4; // 147,456 B
    const int smemC = (128 * 68 + 128 * 132) * 4;                      // 102,400 B

    cudaFuncSetAttribute(kproj_kv, cudaFuncAttributeMaxDynamicSharedMemorySize, smemA);
    cudaFuncSetAttribute(katt,     cudaFuncAttributeMaxDynamicSharedMemorySize, smemB);
    cudaFuncSetAttribute(kout,     cudaFuncAttributeMaxDynamicSharedMemorySize, smemC);

    kdetect <<<1, 32>>>(klist);
    kproj_kv<<<NBLK, 256, smemA>>>(Z, Wk, Wv, Wb);
    katt    <<<NBLK, 256, smemB>>>(Z, Wq, Wg, bg, klist);
    kout    <<<NBLK, 256, smemC>>>(Wout, bout, out);
}

// round 3
// speedup vs baseline: 1.0425x; 1.0425x over previous
#include <cuda_runtime.h>
#include <math.h>

// Problem constants
#define EN      200000
#define IND     128
#define HIDD    32
#define NH      4
#define OUTD    128
#define MAXK    16
#define TM      64                     // rows per block (attention kernel)
#define NBLK    (EN / TM)              // 3125
#define TMP     128                    // rows per block (projection kernel)
#define NBLKP   ((EN + TMP - 1) / TMP) // 1563

// Scratch (device globals; no allocation)
__device__ float g_kv[(size_t)EN * 256];   // [e][0:128]=k (head-major), [128:256]=v
__device__ float g_bh[(size_t)EN * NH];    // [e][h]
__device__ int   g_kstride;                // 2 if klist is int64, 1 if int32

// ---------------------------------------------------------------------------
// Prologue: detect klist element width. int64 viewed as int32 pairs has every
// odd word == 0 or -1 (sign-extension of values in [-1, E)).
// ---------------------------------------------------------------------------
__global__ void kdetect(const int* __restrict__ kw)
{
    if (threadIdx.x == 0 && blockIdx.x == 0) {
        int is64 = 1;
        for (int i = 0; i < 4096; i++) {
            int hi = kw[2 * i + 1];
            if (hi != 0 && hi != -1) { is64 = 0; break; }
        }
        g_kstride = is64 ? 2 : 1;
    }
}

// ---------------------------------------------------------------------------
// Kernel A: KV + b projection. Tile 128 rows x 256 cols, 8x8 register tiles.
// chunk0 = K (cols 0..127), chunk1 = V (cols 128..255).
// ---------------------------------------------------------------------------
__global__ void __launch_bounds__(256, 1) kproj_kv(
    const float* __restrict__ Z,
    const float* __restrict__ Wk,
    const float* __restrict__ Wv,
    const float* __restrict__ Wb)
{
    extern __shared__ float sm[];
    float* sZt = sm;                       // [128 k][132]  (k, row)
    float* sW  = sm + 128 * 132;           // [128 k][132]  (k, col)
    float* sWb = sm + 2 * 128 * 132;       // [512]

    const int tid  = threadIdx.x;
    const int row0 = blockIdx.x * TMP;

    // Load Z tile transposed into smem (clamp OOB rows; stores are guarded)
    for (int i = tid; i < TMP * 32; i += 256) {
        int r = i >> 5, c = i & 31;
        int rg = row0 + r; if (rg >= EN) rg = EN - 1;
        float4 v = *(const float4*)(Z + (size_t)rg * IND + c * 4);
        sZt[(c * 4 + 0) * 132 + r] = v.x;
        sZt[(c * 4 + 1) * 132 + r] = v.y;
        sZt[(c * 4 + 2) * 132 + r] = v.z;
        sZt[(c * 4 + 3) * 132 + r] = v.w;
    }
    for (int i = tid; i < NH * IND; i += 256) sWb[i] = Wb[i];

    const int ty = tid >> 4, tx = tid & 15;

    for (int chunk = 0; chunk < 2; chunk++) {
        __syncthreads();
        const float* Wsrc = chunk ? Wv : Wk;
        for (int i = tid; i < 128 * 32; i += 256) {
            int c = i >> 5, kq = i & 31;
            float4 w = *(const float4*)(Wsrc + (size_t)c * IND + kq * 4);
            sW[(kq * 4 + 0) * 132 + c] = w.x;
            sW[(kq * 4 + 1) * 132 + c] = w.y;
            sW[(kq * 4 + 2) * 132 + c] = w.z;
            sW[(kq * 4 + 3) * 132 + c] = w.w;
        }
        __syncthreads();

        float acc[8][8] = {};
        #pragma unroll 8
        for (int k = 0; k < 128; k++) {
            float4 a0 = *(const float4*)(sZt + k * 132 + ty * 8);
            float4 a1 = *(const float4*)(sZt + k * 132 + ty * 8 + 4);
            float4 b0 = *(const float4*)(sW  + k * 132 + tx * 8);
            float4 b1 = *(const float4*)(sW  + k * 132 + tx * 8 + 4);
            float av[8] = {a0.x, a0.y, a0.z, a0.w, a1.x, a1.y, a1.z, a1.w};
            float bv[8] = {b0.x, b0.y, b0.z, b0.w, b1.x, b1.y, b1.z, b1.w};
            #pragma unroll
            for (int i = 0; i < 8; i++)
                #pragma unroll
                for (int j = 0; j < 8; j++)
                    acc[i][j] += av[i] * bv[j];
        }
        #pragma unroll
        for (int i = 0; i < 8; i++) {
            int rg = row0 + ty * 8 + i;
            if (rg < EN) {
                float* dst = &g_kv[(size_t)rg * 256 + chunk * 128 + tx * 8];
                *(float4*)dst       = make_float4(acc[i][0], acc[i][1], acc[i][2], acc[i][3]);
                *(float4*)(dst + 4) = make_float4(acc[i][4], acc[i][5], acc[i][6], acc[i][7]);
            }
        }
    }

    // b tail: (row, head) dots, 512 items over 256 threads
    for (int t = tid; t < TMP * NH; t += 256) {
        int r = t >> 2, h = t & 3;
        int rg = row0 + r;
        if (rg < EN) {
            float s = 0.f;
            #pragma unroll 8
            for (int k = 0; k < 128; k++) s += sZt[k * 132 + r] * sWb[h * IND + k];
            g_bh[(size_t)rg * NH + h] = s;
        }
    }
}

// ---------------------------------------------------------------------------
// Kernel B (fused): q/g projection + gather attention + gating + output GEMM
// ---------------------------------------------------------------------------
__global__ void __launch_bounds__(256, 1) katt_out(
    const float* __restrict__ Z,
    const float* __restrict__ Wq,
    const float* __restrict__ Wg,
    const float* __restrict__ bg,
    const int*   __restrict__ kw,
    const float* __restrict__ Wout,
    const float* __restrict__ bout,
    float*       __restrict__ out)
{
    extern __shared__ float sm[];
    float* sZt = sm;                          // [128 k][68]  Z^T, later X^T
    float* sW  = sZt + 128 * 68;              // [128 k][132] weights / later Wout^T
    float* sQ  = sW  + 128 * 132;             // [64][136]
    float* sG  = sQ  + 64 * 136;              // [64][136]
    int*   skl = (int*)(sG + 64 * 136);       // [64][32]

    const int tid  = threadIdx.x;
    const int row0 = blockIdx.x * TM;
    const int st   = g_kstride;

    // Load Z tile transposed
    const float4* Z4 = (const float4*)(Z + (size_t)row0 * IND);
    for (int i = tid; i < TM * 32; i += 256) {
        int r = i >> 5, c = i & 31;
        float4 v = Z4[r * 32 + c];
        sZt[(c * 4 + 0) * 68 + r] = v.x;
        sZt[(c * 4 + 1) * 68 + r] = v.y;
        sZt[(c * 4 + 2) * 68 + r] = v.z;
        sZt[(c * 4 + 3) * 68 + r] = v.w;
    }
    // klist words: per-row layout [ii(16) | jj(16)]
    for (int i = tid; i < TM * 32; i += 256)
        skl[i] = kw[((size_t)row0 * 32 + i) * st];

    const int ty = tid >> 4, tx = tid & 15;

    // ---- Phase 1: q (chunk0) and g (chunk1), 4x8 microtiles over 128 cols
    for (int chunk = 0; chunk < 2; chunk++) {
        __syncthreads();
        const float* Wsrc = chunk ? Wg : Wq;
        for (int i = tid; i < 128 * 32; i += 256) {
            int c = i >> 5, kq = i & 31;
            float4 w = *(const float4*)(Wsrc + (size_t)c * IND + kq * 4);
            sW[(kq * 4 + 0) * 132 + c] = w.x;
            sW[(kq * 4 + 1) * 132 + c] = w.y;
            sW[(kq * 4 + 2) * 132 + c] = w.z;
            sW[(kq * 4 + 3) * 132 + c] = w.w;
        }
        __syncthreads();

        float acc[4][8] = {};
        #pragma unroll 8
        for (int k = 0; k < 128; k++) {
            float4 a  = *(const float4*)(sZt + k * 68 + ty * 4);
            float4 b0 = *(const float4*)(sW  + k * 132 + tx * 8);
            float4 b1 = *(const float4*)(sW  + k * 132 + tx * 8 + 4);
            float av[4] = {a.x, a.y, a.z, a.w};
            float bv[8] = {b0.x, b0.y, b0.z, b0.w, b1.x, b1.y, b1.z, b1.w};
            #pragma unroll
            for (int i = 0; i < 4; i++)
                #pragma unroll
                for (int j = 0; j < 8; j++)
                    acc[i][j] += av[i] * bv[j];
        }
        if (chunk == 0) {
            #pragma unroll
            for (int i = 0; i < 4; i++)
                #pragma unroll
                for (int j = 0; j < 8; j++)
                    sQ[(ty * 4 + i) * 136 + tx * 8 + j] = acc[i][j];
        } else {
            #pragma unroll
            for (int i = 0; i < 4; i++)
                #pragma unroll
                for (int j = 0; j < 8; j++) {
                    float x = acc[i][j] + bg[tx * 8 + j];
                    sG[(ty * 4 + i) * 136 + tx * 8 + j] = 1.f / (1.f + expf(-x));
                }
        }
    }
    __syncthreads();   // sQ/sG ready; sZt now dead (reused as X^T below)

    // ---- Phase 2: one thread per (row, head)
    {
        const int r = tid >> 2, h = tid & 3;

        float q[32];
        #pragma unroll
        for (int c = 0; c < 8; c++) {
            float4 t = *(const float4*)&sQ[r * 136 + h * 32 + c * 4];
            q[c * 4 + 0] = t.x; q[c * 4 + 1] = t.y; q[c * 4 + 2] = t.z; q[c * 4 + 3] = t.w;
        }

        const float scale = 0.17677669529663687f;   // 1/sqrt(32)
        float sc[MAXK];
        float m = -1e30f;
        #pragma unroll
        for (int s = 0; s < MAXK; s++) {
            int ii = skl[r * 32 + s];
            float v = 0.f;
            if (ii >= 0) {
                ii = min(ii, EN - 1);
                const float4* kp = (const float4*)&g_kv[(size_t)ii * 256 + h * 32];
                float d = 0.f;
                #pragma unroll
                for (int c = 0; c < 8; c++) {
                    float4 kk = kp[c];
                    d += q[c*4+0]*kk.x + q[c*4+1]*kk.y + q[c*4+2]*kk.z + q[c*4+3]*kk.w;
                }
                int jj = skl[r * 32 + 16 + s];
                jj = min(max(jj, 0), EN - 1);
                v = scale * d + g_bh[(size_t)jj * NH + h];
            }
            sc[s] = v;
            m = fmaxf(m, v);
        }

        float den = 0.f;
        #pragma unroll
        for (int s = 0; s < MAXK; s++) {
            float ex = expf(sc[s] - m);
            sc[s] = ex;
            den += ex;
        }

        float att[32];
        #pragma unroll
        for (int j = 0; j < 32; j++) att[j] = 0.f;

        #pragma unroll
        for (int s = 0; s < MAXK; s++) {
            int ii = skl[r * 32 + s];
            if (ii >= 0) {
                ii = min(ii, EN - 1);
                const float4* vp = (const float4*)&g_kv[(size_t)ii * 256 + 128 + h * 32];
                float w = sc[s];
                #pragma unroll
                for (int c = 0; c < 8; c++) {
                    float4 vv = vp[c];
                    att[c*4+0] += w * vv.x; att[c*4+1] += w * vv.y;
                    att[c*4+2] += w * vv.z; att[c*4+3] += w * vv.w;
                }
            }
        }

        // gated X, stored TRANSPOSED into sZt region: sXt[col][row]
        const float inv = 1.f / den;
        #pragma unroll
        for (int c = 0; c < 32; c++) {
            float gv = sG[r * 136 + h * 32 + c];
            sZt[(h * 32 + c) * 68 + r] = gv * att[c] * inv;
        }
    }

    // Load Wout^T into sW region (dead after phase 1): sWt[k][outcol]
    const float4* W4 = (const float4*)Wout;
    for (int i = tid; i < 128 * 32; i += 256) {
        int o = i >> 5, kq = i & 31;
        float4 w = W4[o * 32 + kq];
        sW[(kq * 4 + 0) * 132 + o] = w.x;
        sW[(kq * 4 + 1) * 132 + o] = w.y;
        sW[(kq * 4 + 2) * 132 + o] = w.z;
        sW[(kq * 4 + 3) * 132 + o] = w.w;
    }
    __syncthreads();

    // ---- Phase 3: out = X @ Wout^T + bout, 4x8 microtiles
    float acc[4][8] = {};
    #pragma unroll 4
    for (int k = 0; k < 128; k++) {
        float4 a  = *(const float4*)(sZt + k * 68 + ty * 4);
        float4 b0 = *(const float4*)(sW  + k * 132 + tx * 8);
        float4 b1 = *(const float4*)(sW  + k * 132 + tx * 8 + 4);
        float av[4] = {a.x, a.y, a.z, a.w};
        float bv[8] = {b0.x, b0.y, b0.z, b0.w, b1.x, b1.y, b1.z, b1.w};
        #pragma unroll
        for (int i = 0; i < 4; i++)
            #pragma unroll
            for (int j = 0; j < 8; j++)
                acc[i][j] += av[i] * bv[j];
    }

    float bb[8];
    #pragma unroll
    for (int j = 0; j < 8; j++) bb[j] = bout[tx * 8 + j];

    #pragma unroll
    for (int i = 0; i < 4; i++) {
        size_t e = (size_t)(row0 + ty * 4 + i);
        float4 o0 = make_float4(acc[i][0] + bb[0], acc[i][1] + bb[1],
                                acc[i][2] + bb[2], acc[i][3] + bb[3]);
        float4 o1 = make_float4(acc[i][4] + bb[4], acc[i][5] + bb[5],
                                acc[i][6] + bb[6], acc[i][7] + bb[7]);
        *(float4*)&out[e * 128 + tx * 8]     = o0;
        *(float4*)&out[e * 128 + tx * 8 + 4] = o1;
    }
}

// ---------------------------------------------------------------------------
extern "C" void kernel_launch(void* const* d_in, const int* in_sizes, int n_in,
                              void* d_out, int out_size)
{
    // Locate Z and klist by element count; remaining inputs keep dict order:
    // Wq, Wk, Wv, Wb, Wg, bg, Wout, bout
    const float* Z = nullptr;
    const int*   klist = nullptr;
    const void*  rest[16];
    int nrest = 0;
    for (int i = 0; i < n_in; i++) {
        if (in_sizes[i] == 25600000)      Z     = (const float*)d_in[i];
        else if (in_sizes[i] == 6400000)  klist = (const int*)d_in[i];
        else                              rest[nrest++] = d_in[i];
    }
    const float* Wq   = (const float*)rest[0];
    const float* Wk   = (const float*)rest[1];
    const float* Wv   = (const float*)rest[2];
    const float* Wb   = (const float*)rest[3];
    const float* Wg   = (const float*)rest[4];
    const float* bg   = (const float*)rest[5];
    const float* Wout = (const float*)rest[6];
    const float* bout = (const float*)rest[7];
    float* out = (float*)d_out;

    const int smemA = (2 * 128 * 132 + 512) * 4;                         // 137,216 B
    const int smemB = (128 * 68 + 128 * 132 + 2 * 64 * 136) * 4 + TM * 32 * 4; // 180,224 B

    cudaFuncSetAttribute(kproj_kv, cudaFuncAttributeMaxDynamicSharedMemorySize, smemA);
    cudaFuncSetAttribute(katt_out, cudaFuncAttributeMaxDynamicSharedMemorySize, smemB);

    kdetect <<<1, 32>>>(klist);
    kproj_kv<<<NBLKP, 256, smemA>>>(Z, Wk, Wv, Wb);
    katt_out<<<NBLK, 256, smemB>>>(Z, Wq, Wg, bg, klist, Wout, bout, out);
}

// round 4
// speedup vs baseline: 1.1734x; 1.1256x over previous
#include <cuda_runtime.h>
#include <cuda_fp16.h>
#include <math.h>

// Problem constants
#define EN      200000
#define IND     128
#define HIDD    32
#define NH      4
#define OUTD    128
#define MAXK    16
#define TM      64                     // rows per block (attention kernel)
#define NBLK    (EN / TM)              // 3125
#define TMP     128                    // rows per block (projection kernel)
#define NBLKP   ((EN + TMP - 1) / TMP) // 1563

// Scratch (device globals; no allocation)
__device__ __half g_kv[(size_t)EN * 256];  // [e][0:128]=k (head-major), [128:256]=v  (fp16)
__device__ float  g_bh[(size_t)EN * NH];   // [e][h]
__device__ int    g_kstride;               // 2 if klist is int64, 1 if int32

// ---------------------------------------------------------------------------
// Prologue: detect klist element width. int64 viewed as int32 pairs has every
// odd word == 0 or -1 (sign-extension of values in [-1, E)).
// ---------------------------------------------------------------------------
__global__ void kdetect(const int* __restrict__ kw)
{
    if (threadIdx.x == 0 && blockIdx.x == 0) {
        int is64 = 1;
        for (int i = 0; i < 4096; i++) {
            int hi = kw[2 * i + 1];
            if (hi != 0 && hi != -1) { is64 = 0; break; }
        }
        g_kstride = is64 ? 2 : 1;
    }
}

// ---------------------------------------------------------------------------
// Kernel A: KV + b projection. Tile 128 rows x 256 cols, 8x8 register tiles.
// chunk0 = K (cols 0..127), chunk1 = V (cols 128..255). Output fp16.
// ---------------------------------------------------------------------------
__global__ void __launch_bounds__(256, 1) kproj_kv(
    const float* __restrict__ Z,
    const float* __restrict__ Wk,
    const float* __restrict__ Wv,
    const float* __restrict__ Wb)
{
    extern __shared__ float sm[];
    float* sZt = sm;                       // [128 k][132]  (k, row)
    float* sW  = sm + 128 * 132;           // [128 k][132]  (k, col)
    float* sWb = sm + 2 * 128 * 132;       // [512]

    const int tid  = threadIdx.x;
    const int row0 = blockIdx.x * TMP;

    // Load Z tile transposed into smem (clamp OOB rows; stores are guarded)
    for (int i = tid; i < TMP * 32; i += 256) {
        int r = i >> 5, c = i & 31;
        int rg = row0 + r; if (rg >= EN) rg = EN - 1;
        float4 v = *(const float4*)(Z + (size_t)rg * IND + c * 4);
        sZt[(c * 4 + 0) * 132 + r] = v.x;
        sZt[(c * 4 + 1) * 132 + r] = v.y;
        sZt[(c * 4 + 2) * 132 + r] = v.z;
        sZt[(c * 4 + 3) * 132 + r] = v.w;
    }
    for (int i = tid; i < NH * IND; i += 256) sWb[i] = Wb[i];

    const int ty = tid >> 4, tx = tid & 15;

    for (int chunk = 0; chunk < 2; chunk++) {
        __syncthreads();
        const float* Wsrc = chunk ? Wv : Wk;
        for (int i = tid; i < 128 * 32; i += 256) {
            int c = i >> 5, kq = i & 31;
            float4 w = *(const float4*)(Wsrc + (size_t)c * IND + kq * 4);
            sW[(kq * 4 + 0) * 132 + c] = w.x;
            sW[(kq * 4 + 1) * 132 + c] = w.y;
            sW[(kq * 4 + 2) * 132 + c] = w.z;
            sW[(kq * 4 + 3) * 132 + c] = w.w;
        }
        __syncthreads();

        float acc[8][8] = {};
        #pragma unroll 8
        for (int k = 0; k < 128; k++) {
            float4 a0 = *(const float4*)(sZt + k * 132 + ty * 8);
            float4 a1 = *(const float4*)(sZt + k * 132 + ty * 8 + 4);
            float4 b0 = *(const float4*)(sW  + k * 132 + tx * 8);
            float4 b1 = *(const float4*)(sW  + k * 132 + tx * 8 + 4);
            float av[8] = {a0.x, a0.y, a0.z, a0.w, a1.x, a1.y, a1.z, a1.w};
            float bv[8] = {b0.x, b0.y, b0.z, b0.w, b1.x, b1.y, b1.z, b1.w};
            #pragma unroll
            for (int i = 0; i < 8; i++)
                #pragma unroll
                for (int j = 0; j < 8; j++)
                    acc[i][j] += av[i] * bv[j];
        }
        #pragma unroll
        for (int i = 0; i < 8; i++) {
            int rg = row0 + ty * 8 + i;
            if (rg < EN) {
                __half h8[8];
                #pragma unroll
                for (int j = 0; j < 8; j++) h8[j] = __float2half_rn(acc[i][j]);
                *(uint4*)&g_kv[(size_t)rg * 256 + chunk * 128 + tx * 8] = *(uint4*)h8;
            }
        }
    }

    // b tail: (row, head) dots, 512 items over 256 threads
    for (int t = tid; t < TMP * NH; t += 256) {
        int r = t >> 2, h = t & 3;
        int rg = row0 + r;
        if (rg < EN) {
            float s = 0.f;
            #pragma unroll 8
            for (int k = 0; k < 128; k++) s += sZt[k * 132 + r] * sWb[h * IND + k];
            g_bh[(size_t)rg * NH + h] = s;
        }
    }
}

// ---------------------------------------------------------------------------
// Kernel B (fused): q/g projection + gather attention + gating + output GEMM
// ---------------------------------------------------------------------------
__global__ void __launch_bounds__(256, 1) katt_out(
    const float* __restrict__ Z,
    const float* __restrict__ Wq,
    const float* __restrict__ Wg,
    const float* __restrict__ bg,
    const int*   __restrict__ kw,
    const float* __restrict__ Wout,
    const float* __restrict__ bout,
    float*       __restrict__ out)
{
    extern __shared__ float sm[];
    float* sZt = sm;                          // [128 k][68]  Z^T, later X^T
    float* sW  = sZt + 128 * 68;              // [128 k][132] weights / later Wout^T
    float* sQ  = sW  + 128 * 132;             // [64][136]
    float* sG  = sQ  + 64 * 136;              // [64][136]
    int*   skl = (int*)(sG + 64 * 136);       // [64][32]

    const int tid  = threadIdx.x;
    const int row0 = blockIdx.x * TM;
    const int st   = g_kstride;

    // Load Z tile transposed
    const float4* Z4 = (const float4*)(Z + (size_t)row0 * IND);
    for (int i = tid; i < TM * 32; i += 256) {
        int r = i >> 5, c = i & 31;
        float4 v = Z4[r * 32 + c];
        sZt[(c * 4 + 0) * 68 + r] = v.x;
        sZt[(c * 4 + 1) * 68 + r] = v.y;
        sZt[(c * 4 + 2) * 68 + r] = v.z;
        sZt[(c * 4 + 3) * 68 + r] = v.w;
    }
    // klist words: per-row layout [ii(16) | jj(16)]
    for (int i = tid; i < TM * 32; i += 256)
        skl[i] = kw[((size_t)row0 * 32 + i) * st];

    const int ty = tid >> 4, tx = tid & 15;

    // ---- Phase 1: q (chunk0) and g (chunk1), 4x8 microtiles over 128 cols
    for (int chunk = 0; chunk < 2; chunk++) {
        __syncthreads();
        const float* Wsrc = chunk ? Wg : Wq;
        for (int i = tid; i < 128 * 32; i += 256) {
            int c = i >> 5, kq = i & 31;
            float4 w = *(const float4*)(Wsrc + (size_t)c * IND + kq * 4);
            sW[(kq * 4 + 0) * 132 + c] = w.x;
            sW[(kq * 4 + 1) * 132 + c] = w.y;
            sW[(kq * 4 + 2) * 132 + c] = w.z;
            sW[(kq * 4 + 3) * 132 + c] = w.w;
        }
        __syncthreads();

        float acc[4][8] = {};
        #pragma unroll 8
        for (int k = 0; k < 128; k++) {
            float4 a  = *(const float4*)(sZt + k * 68 + ty * 4);
            float4 b0 = *(const float4*)(sW  + k * 132 + tx * 8);
            float4 b1 = *(const float4*)(sW  + k * 132 + tx * 8 + 4);
            float av[4] = {a.x, a.y, a.z, a.w};
            float bv[8] = {b0.x, b0.y, b0.z, b0.w, b1.x, b1.y, b1.z, b1.w};
            #pragma unroll
            for (int i = 0; i < 4; i++)
                #pragma unroll
                for (int j = 0; j < 8; j++)
                    acc[i][j] += av[i] * bv[j];
        }
        if (chunk == 0) {
            #pragma unroll
            for (int i = 0; i < 4; i++)
                #pragma unroll
                for (int j = 0; j < 8; j++)
                    sQ[(ty * 4 + i) * 136 + tx * 8 + j] = acc[i][j];
        } else {
            #pragma unroll
            for (int i = 0; i < 4; i++)
                #pragma unroll
                for (int j = 0; j < 8; j++) {
                    float x = acc[i][j] + bg[tx * 8 + j];
                    sG[(ty * 4 + i) * 136 + tx * 8 + j] = 1.f / (1.f + expf(-x));
                }
        }
    }
    __syncthreads();   // sQ/sG ready; sZt now dead (reused as X^T below)

    // ---- Phase 2: one thread per (row, head), fp16 KV gathers
    {
        const int r = tid >> 2, h = tid & 3;

        float q[32];
        #pragma unroll
        for (int c = 0; c < 8; c++) {
            float4 t = *(const float4*)&sQ[r * 136 + h * 32 + c * 4];
            q[c * 4 + 0] = t.x; q[c * 4 + 1] = t.y; q[c * 4 + 2] = t.z; q[c * 4 + 3] = t.w;
        }

        const float scale = 0.17677669529663687f;   // 1/sqrt(32)
        float sc[MAXK];
        float m = -1e30f;
        #pragma unroll
        for (int s = 0; s < MAXK; s++) {
            int ii = skl[r * 32 + s];
            float v = 0.f;
            if (ii >= 0) {
                ii = min(ii, EN - 1);
                const uint4* kp = (const uint4*)&g_kv[(size_t)ii * 256 + h * 32];
                float d = 0.f;
                #pragma unroll
                for (int c = 0; c < 4; c++) {          // 4 x 8 halfs
                    uint4 u = kp[c];
                    const __half2* hp = (const __half2*)&u;
                    #pragma unroll
                    for (int p = 0; p < 4; p++) {
                        float2 f = __half22float2(hp[p]);
                        d += q[c*8 + p*2 + 0] * f.x + q[c*8 + p*2 + 1] * f.y;
                    }
                }
                int jj = skl[r * 32 + 16 + s];
                jj = min(max(jj, 0), EN - 1);
                v = scale * d + g_bh[(size_t)jj * NH + h];
            }
            sc[s] = v;
            m = fmaxf(m, v);
        }

        float den = 0.f;
        #pragma unroll
        for (int s = 0; s < MAXK; s++) {
            float ex = expf(sc[s] - m);
            sc[s] = ex;
            den += ex;
        }

        float att[32];
        #pragma unroll
        for (int j = 0; j < 32; j++) att[j] = 0.f;

        #pragma unroll
        for (int s = 0; s < MAXK; s++) {
            int ii = skl[r * 32 + s];
            if (ii >= 0) {
                ii = min(ii, EN - 1);
                const uint4* vp = (const uint4*)&g_kv[(size_t)ii * 256 + 128 + h * 32];
                float w = sc[s];
                #pragma unroll
                for (int c = 0; c < 4; c++) {
                    uint4 u = vp[c];
                    const __half2* hp = (const __half2*)&u;
                    #pragma unroll
                    for (int p = 0; p < 4; p++) {
                        float2 f = __half22float2(hp[p]);
                        att[c*8 + p*2 + 0] += w * f.x;
                        att[c*8 + p*2 + 1] += w * f.y;
                    }
                }
            }
        }

        // gated X, stored TRANSPOSED into sZt region: sXt[col][row]
        const float inv = 1.f / den;
        #pragma unroll
        for (int c = 0; c < 32; c++) {
            float gv = sG[r * 136 + h * 32 + c];
            sZt[(h * 32 + c) * 68 + r] = gv * att[c] * inv;
        }
    }

    // Load Wout^T into sW region (dead after phase 1): sWt[k][outcol]
    const float4* W4 = (const float4*)Wout;
    for (int i = tid; i < 128 * 32; i += 256) {
        int o = i >> 5, kq = i & 31;
        float4 w = W4[o * 32 + kq];
        sW[(kq * 4 + 0) * 132 + o] = w.x;
        sW[(kq * 4 + 1) * 132 + o] = w.y;
        sW[(kq * 4 + 2) * 132 + o] = w.z;
        sW[(kq * 4 + 3) * 132 + o] = w.w;
    }
    __syncthreads();

    // ---- Phase 3: out = X @ Wout^T + bout, 4x8 microtiles
    float acc[4][8] = {};
    #pragma unroll 4
    for (int k = 0; k < 128; k++) {
        float4 a  = *(const float4*)(sZt + k * 68 + ty * 4);
        float4 b0 = *(const float4*)(sW  + k * 132 + tx * 8);
        float4 b1 = *(const float4*)(sW  + k * 132 + tx * 8 + 4);
        float av[4] = {a.x, a.y, a.z, a.w};
        float bv[8] = {b0.x, b0.y, b0.z, b0.w, b1.x, b1.y, b1.z, b1.w};
        #pragma unroll
        for (int i = 0; i < 4; i++)
            #pragma unroll
            for (int j = 0; j < 8; j++)
                acc[i][j] += av[i] * bv[j];
    }

    float bb[8];
    #pragma unroll
    for (int j = 0; j < 8; j++) bb[j] = bout[tx * 8 + j];

    #pragma unroll
    for (int i = 0; i < 4; i++) {
        size_t e = (size_t)(row0 + ty * 4 + i);
        float4 o0 = make_float4(acc[i][0] + bb[0], acc[i][1] + bb[1],
                                acc[i][2] + bb[2], acc[i][3] + bb[3]);
        float4 o1 = make_float4(acc[i][4] + bb[4], acc[i][5] + bb[5],
                                acc[i][6] + bb[6], acc[i][7] + bb[7]);
        *(float4*)&out[e * 128 + tx * 8]     = o0;
        *(float4*)&out[e * 128 + tx * 8 + 4] = o1;
    }
}

// ---------------------------------------------------------------------------
extern "C" void kernel_launch(void* const* d_in, const int* in_sizes, int n_in,
                              void* d_out, int out_size)
{
    // Locate Z and klist by element count; remaining inputs keep dict order:
    // Wq, Wk, Wv, Wb, Wg, bg, Wout, bout
    const float* Z = nullptr;
    const int*   klist = nullptr;
    const void*  rest[16];
    int nrest = 0;
    for (int i = 0; i < n_in; i++) {
        if (in_sizes[i] == 25600000)      Z     = (const float*)d_in[i];
        else if (in_sizes[i] == 6400000)  klist = (const int*)d_in[i];
        else                              rest[nrest++] = d_in[i];
    }
    const float* Wq   = (const float*)rest[0];
    const float* Wk   = (const float*)rest[1];
    const float* Wv   = (const float*)rest[2];
    const float* Wb   = (const float*)rest[3];
    const float* Wg   = (const float*)rest[4];
    const float* bg   = (const float*)rest[5];
    const float* Wout = (const float*)rest[6];
    const float* bout = (const float*)rest[7];
    float* out = (float*)d_out;

    const int smemA = (2 * 128 * 132 + 512) * 4;                         // 137,216 B
    const int smemB = (128 * 68 + 128 * 132 + 2 * 64 * 136) * 4 + TM * 32 * 4; // 180,224 B

    cudaFuncSetAttribute(kproj_kv, cudaFuncAttributeMaxDynamicSharedMemorySize, smemA);
    cudaFuncSetAttribute(katt_out, cudaFuncAttributeMaxDynamicSharedMemorySize, smemB);

    kdetect <<<1, 32>>>(klist);
    kproj_kv<<<NBLKP, 256, smemA>>>(Z, Wk, Wv, Wb);
    katt_out<<<NBLK, 256, smemB>>>(Z, Wq, Wg, bg, klist, Wout, bout, out);
}

// round 6
// speedup vs baseline: 3.5794x; 3.0504x over previous
#include <cuda_runtime.h>
#include <cuda_fp16.h>
#include <math.h>
#include <stdint.h>

// Problem constants
#define EN      200000
#define IND     128
#define HIDD    32
#define NH      4
#define OUTD    128
#define MAXK    16
#define TM      64                     // rows per block (attention kernel)
#define NBLK    (EN / TM)              // 3125
#define TMP     128                    // rows per block (projection kernel)
#define NBLKP   ((EN + TMP - 1) / TMP) // 1563
#define SH      136                    // smem row stride in halfs (128 + 8 pad)

// Scratch (device globals; no allocation)
__device__ __half g_kv[(size_t)EN * 256];  // [e][0:128]=k (head-major), [128:256]=v
__device__ float  g_bh[(size_t)EN * NH];   // [e][h]
__device__ int    g_kstride;               // 2 if klist is int64, 1 if int32

// m16n8k16 f16 MMA, fp32 accum. A row-major frag, B col-major frag.
__device__ __forceinline__ void mma16816(float c[4], unsigned a0, unsigned a1,
                                         unsigned a2, unsigned a3,
                                         unsigned b0, unsigned b1)
{
    asm volatile(
        "mma.sync.aligned.m16n8k16.row.col.f32.f16.f16.f32 "
        "{%0,%1,%2,%3}, {%4,%5,%6,%7}, {%8,%9}, {%0,%1,%2,%3};\n"
        : "+f"(c[0]), "+f"(c[1]), "+f"(c[2]), "+f"(c[3])
        : "r"(a0), "r"(a1), "r"(a2), "r"(a3), "r"(b0), "r"(b1));
}

__device__ __forceinline__ unsigned ldh2(const __half* p) { return *(const unsigned*)p; }

// ---------------------------------------------------------------------------
// Kernel A: KV + b projection (fp16 HMMA). Tile 128 rows; 8 warps, each warp
// 16 rows x 128 cols per chunk (16 n-tiles). chunk0=K, chunk1=V. Also detects
// klist width (block 0) and computes b = Z@Wb per head.
// ---------------------------------------------------------------------------
__global__ void __launch_bounds__(256, 2) kproj_kv(
    const float* __restrict__ Z,
    const float* __restrict__ Wk,
    const float* __restrict__ Wv,
    const float* __restrict__ Wb,
    const int*   __restrict__ kw)
{
    extern __shared__ __half sh[];
    __half* sZ  = sh;                 // [128][SH]  A (row-major m x k)
    __half* sW  = sh + 128 * SH;      // [128][SH]  B (n-major n x k)
    __half* sWb = sh + 2 * 128 * SH;  // [4][128]

    const int tid  = threadIdx.x;
    const int row0 = blockIdx.x * TMP;

    // klist width detection (once, block 0)
    if (blockIdx.x == 0 && tid == 0) {
        int is64 = 1;
        for (int i = 0; i < 4096; i++) {
            int hi = kw[2 * i + 1];
            if (hi != 0 && hi != -1) { is64 = 0; break; }
        }
        g_kstride = is64 ? 2 : 1;
    }

    // Load Z tile (fp32 -> fp16), row-major
    for (int i = tid; i < TMP * 32; i += 256) {
        int r = i >> 5, c = i & 31;
        int rg = row0 + r; if (rg >= EN) rg = EN - 1;
        float4 v = *(const float4*)(Z + (size_t)rg * IND + c * 4);
        *(__half2*)&sZ[r * SH + c * 4]     = __floats2half2_rn(v.x, v.y);
        *(__half2*)&sZ[r * SH + c * 4 + 2] = __floats2half2_rn(v.z, v.w);
    }
    for (int i = tid; i < NH * IND; i += 256) sWb[i] = __float2half_rn(Wb[i]);

    const int lane = tid & 31, wid = tid >> 5;
    const int g = lane >> 2, tig = lane & 3;
    const int rw = wid * 16;

    for (int chunk = 0; chunk < 2; chunk++) {
        __syncthreads();
        const float* Wsrc = chunk ? Wv : Wk;
        for (int i = tid; i < 128 * 32; i += 256) {
            int c = i >> 5, kq = i & 31;
            float4 w = *(const float4*)(Wsrc + (size_t)c * IND + kq * 4);
            *(__half2*)&sW[c * SH + kq * 4]     = __floats2half2_rn(w.x, w.y);
            *(__half2*)&sW[c * SH + kq * 4 + 2] = __floats2half2_rn(w.z, w.w);
        }
        __syncthreads();

        float acc[16][4] = {};
        #pragma unroll
        for (int k0 = 0; k0 < 8; k0++) {
            const __half* pa = sZ + (rw + g) * SH + k0 * 16 + tig * 2;
            unsigned a0 = ldh2(pa);
            unsigned a1 = ldh2(pa + 8 * SH);
            unsigned a2 = ldh2(pa + 8);
            unsigned a3 = ldh2(pa + 8 * SH + 8);
            #pragma unroll
            for (int nt = 0; nt < 16; nt++) {
                const __half* pb = sW + (nt * 8 + g) * SH + k0 * 16 + tig * 2;
                mma16816(acc[nt], a0, a1, a2, a3, ldh2(pb), ldh2(pb + 8));
            }
        }

        int r0g = row0 + rw + g;
        #pragma unroll
        for (int nt = 0; nt < 16; nt++) {
            int col = chunk * 128 + nt * 8 + tig * 2;
            if (r0g < EN)
                *(__half2*)&g_kv[(size_t)r0g * 256 + col] =
                    __floats2half2_rn(acc[nt][0], acc[nt][1]);
            if (r0g + 8 < EN)
                *(__half2*)&g_kv[(size_t)(r0g + 8) * 256 + col] =
                    __floats2half2_rn(acc[nt][2], acc[nt][3]);
        }
    }

    // b tail: 512 (row, head) dots over fp16 Z
    for (int t = tid; t < TMP * NH; t += 256) {
        int r = t >> 2, h = t & 3;
        int rg = row0 + r;
        if (rg < EN) {
            float s = 0.f;
            #pragma unroll 8
            for (int k = 0; k < 128; k += 2) {
                float2 a = __half22float2(*(__half2*)&sZ[r * SH + k]);
                float2 b = __half22float2(*(__half2*)&sWb[h * IND + k]);
                s += a.x * b.x + a.y * b.y;
            }
            g_bh[(size_t)rg * NH + h] = s;
        }
    }
}

// ---------------------------------------------------------------------------
// Kernel B (fused): q/g projection (HMMA) + gather attention + gating +
// output GEMM (HMMA). 64 rows per block, 8 warps (4m x 2n per GEMM).
// ---------------------------------------------------------------------------
__global__ void __launch_bounds__(256, 2) katt_out(
    const float* __restrict__ Z,
    const float* __restrict__ Wq,
    const float* __restrict__ Wg,
    const float* __restrict__ bg,
    const int*   __restrict__ kw,
    const float* __restrict__ Wout,
    const float* __restrict__ bout,
    float*       __restrict__ out)
{
    extern __shared__ __half sh[];
    __half* sZ  = sh;                  // [64][SH]   Z (A), later X (A)
    __half* sW  = sh + 64 * SH;        // [128][SH]  Wq/Wg, later Wout
    __half* sQ  = sh + 192 * SH;       // [64][SH]
    __half* sG  = sh + 256 * SH;       // [64][SH]
    int*    skl = (int*)(sh + 320 * SH);        // [64][32]
    float*  sbg = (float*)(skl + 2048);         // [128]
    float*  sbo = sbg + 128;                    // [128]

    const int tid  = threadIdx.x;
    const int row0 = blockIdx.x * TM;
    const int st   = g_kstride;

    // Load Z tile (fp32 -> fp16)
    for (int i = tid; i < TM * 32; i += 256) {
        int r = i >> 5, c = i & 31;
        float4 v = *(const float4*)(Z + (size_t)(row0 + r) * IND + c * 4);
        *(__half2*)&sZ[r * SH + c * 4]     = __floats2half2_rn(v.x, v.y);
        *(__half2*)&sZ[r * SH + c * 4 + 2] = __floats2half2_rn(v.z, v.w);
    }
    for (int i = tid; i < TM * 32; i += 256)
        skl[i] = kw[((size_t)row0 * 32 + i) * st];
    for (int i = tid; i < 128; i += 256) { sbg[i] = bg[i]; sbo[i] = bout[i]; }

    const int lane = tid & 31, wid = tid >> 5;
    const int g = lane >> 2, tig = lane & 3;
    const int rw = (wid & 3) * 16;     // warp row offset (0..48)
    const int cw = (wid >> 2) * 64;    // warp col offset (0,64)

    // ---- Phase 1: Q (chunk0) and G (chunk1)
    for (int chunk = 0; chunk < 2; chunk++) {
        __syncthreads();
        const float* Wsrc = chunk ? Wg : Wq;
        for (int i = tid; i < 128 * 32; i += 256) {
            int c = i >> 5, kq = i & 31;
            float4 w = *(const float4*)(Wsrc + (size_t)c * IND + kq * 4);
            *(__half2*)&sW[c * SH + kq * 4]     = __floats2half2_rn(w.x, w.y);
            *(__half2*)&sW[c * SH + kq * 4 + 2] = __floats2half2_rn(w.z, w.w);
        }
        __syncthreads();

        float acc[8][4] = {};
        #pragma unroll
        for (int k0 = 0; k0 < 8; k0++) {
            const __half* pa = sZ + (rw + g) * SH + k0 * 16 + tig * 2;
            unsigned a0 = ldh2(pa);
            unsigned a1 = ldh2(pa + 8 * SH);
            unsigned a2 = ldh2(pa + 8);
            unsigned a3 = ldh2(pa + 8 * SH + 8);
            #pragma unroll
            for (int nt = 0; nt < 8; nt++) {
                const __half* pb = sW + (cw + nt * 8 + g) * SH + k0 * 16 + tig * 2;
                mma16816(acc[nt], a0, a1, a2, a3, ldh2(pb), ldh2(pb + 8));
            }
        }

        if (chunk == 0) {
            #pragma unroll
            for (int nt = 0; nt < 8; nt++) {
                int col = cw + nt * 8 + tig * 2;
                *(__half2*)&sQ[(rw + g) * SH + col]     = __floats2half2_rn(acc[nt][0], acc[nt][1]);
                *(__half2*)&sQ[(rw + g + 8) * SH + col] = __floats2half2_rn(acc[nt][2], acc[nt][3]);
            }
        } else {
            #pragma unroll
            for (int nt = 0; nt < 8; nt++) {
                int col = cw + nt * 8 + tig * 2;
                float g0 = 1.f / (1.f + expf(-(acc[nt][0] + sbg[col])));
                float g1 = 1.f / (1.f + expf(-(acc[nt][1] + sbg[col + 1])));
                float g2 = 1.f / (1.f + expf(-(acc[nt][2] + sbg[col])));
                float g3 = 1.f / (1.f + expf(-(acc[nt][3] + sbg[col + 1])));
                *(__half2*)&sG[(rw + g) * SH + col]     = __floats2half2_rn(g0, g1);
                *(__half2*)&sG[(rw + g + 8) * SH + col] = __floats2half2_rn(g2, g3);
            }
        }
    }
    __syncthreads();   // sQ/sG ready; sZ (A) and sW (B) now dead

    // Stage Wout into sW (overlaps with gather latency below)
    const float4* W4 = (const float4*)Wout;
    for (int i = tid; i < 128 * 32; i += 256) {
        int o = i >> 5, kq = i & 31;
        float4 w = W4[o * 32 + kq];
        *(__half2*)&sW[o * SH + kq * 4]     = __floats2half2_rn(w.x, w.y);
        *(__half2*)&sW[o * SH + kq * 4 + 2] = __floats2half2_rn(w.z, w.w);
    }

    // ---- Phase 2: one thread per (row, head); fp16 KV gathers; X -> sZ
    {
        const int r = tid >> 2, h = tid & 3;

        float q[32];
        #pragma unroll
        for (int c = 0; c < 16; c++) {
            float2 f = __half22float2(*(__half2*)&sQ[r * SH + h * 32 + c * 2]);
            q[c * 2] = f.x; q[c * 2 + 1] = f.y;
        }

        const float scale = 0.17677669529663687f;   // 1/sqrt(32)
        float sc[MAXK];
        float m = -1e30f;
        #pragma unroll
        for (int s = 0; s < MAXK; s++) {
            int ii = skl[r * 32 + s];
            float v = 0.f;
            if (ii >= 0) {
                ii = min(ii, EN - 1);
                const uint4* kp = (const uint4*)&g_kv[(size_t)ii * 256 + h * 32];
                float d = 0.f;
                #pragma unroll
                for (int c = 0; c < 4; c++) {
                    uint4 u = kp[c];
                    const __half2* hp = (const __half2*)&u;
                    #pragma unroll
                    for (int p = 0; p < 4; p++) {
                        float2 f = __half22float2(hp[p]);
                        d += q[c*8 + p*2 + 0] * f.x + q[c*8 + p*2 + 1] * f.y;
                    }
                }
                int jj = skl[r * 32 + 16 + s];
                jj = min(max(jj, 0), EN - 1);
                v = scale * d + g_bh[(size_t)jj * NH + h];
            }
            sc[s] = v;
            m = fmaxf(m, v);
        }

        float den = 0.f;
        #pragma unroll
        for (int s = 0; s < MAXK; s++) {
            float ex = expf(sc[s] - m);
            sc[s] = ex;
            den += ex;
        }

        float att[32];
        #pragma unroll
        for (int j = 0; j < 32; j++) att[j] = 0.f;

        #pragma unroll
        for (int s = 0; s < MAXK; s++) {
            int ii = skl[r * 32 + s];
            if (ii >= 0) {
                ii = min(ii, EN - 1);
                const uint4* vp = (const uint4*)&g_kv[(size_t)ii * 256 + 128 + h * 32];
                float w = sc[s];
                #pragma unroll
                for (int c = 0; c < 4; c++) {
                    uint4 u = vp[c];
                    const __half2* hp = (const __half2*)&u;
                    #pragma unroll
                    for (int p = 0; p < 4; p++) {
                        float2 f = __half22float2(hp[p]);
                        att[c*8 + p*2 + 0] += w * f.x;
                        att[c*8 + p*2 + 1] += w * f.y;
                    }
                }
            }
        }

        // gated X -> sZ (A for phase 3), fp16
        const float inv = 1.f / den;
        #pragma unroll
        for (int c = 0; c < 16; c++) {
            float2 gf = __half22float2(*(__half2*)&sG[r * SH + h * 32 + c * 2]);
            *(__half2*)&sZ[r * SH + h * 32 + c * 2] =
                __floats2half2_rn(gf.x * att[c*2] * inv, gf.y * att[c*2+1] * inv);
        }
    }
    __syncthreads();

    // ---- Phase 3: out = X @ Wout^T + bout
    float acc[8][4] = {};
    #pragma unroll
    for (int k0 = 0; k0 < 8; k0++) {
        const __half* pa = sZ + (rw + g) * SH + k0 * 16 + tig * 2;
        unsigned a0 = ldh2(pa);
        unsigned a1 = ldh2(pa + 8 * SH);
        unsigned a2 = ldh2(pa + 8);
        unsigned a3 = ldh2(pa + 8 * SH + 8);
        #pragma unroll
        for (int nt = 0; nt < 8; nt++) {
            const __half* pb = sW + (cw + nt * 8 + g) * SH + k0 * 16 + tig * 2;
            mma16816(acc[nt], a0, a1, a2, a3, ldh2(pb), ldh2(pb + 8));
        }
    }

    #pragma unroll
    for (int nt = 0; nt < 8; nt++) {
        int col = cw + nt * 8 + tig * 2;
        size_t e0 = (size_t)(row0 + rw + g);
        float2 o0 = make_float2(acc[nt][0] + sbo[col], acc[nt][1] + sbo[col + 1]);
        float2 o1 = make_float2(acc[nt][2] + sbo[col], acc[nt][3] + sbo[col + 1]);
        *(float2*)&out[e0 * 128 + col]       = o0;
        *(float2*)&out[(e0 + 8) * 128 + col] = o1;
    }
}

// ---------------------------------------------------------------------------
extern "C" void kernel_launch(void* const* d_in, const int* in_sizes, int n_in,
                              void* d_out, int out_size)
{
    // Locate Z and klist by element count; remaining inputs keep dict order:
    // Wq, Wk, Wv, Wb, Wg, bg, Wout, bout
    const float* Z = nullptr;
    const int*   klist = nullptr;
    const void*  rest[16];
    int nrest = 0;
    for (int i = 0; i < n_in; i++) {
        if (in_sizes[i] == 25600000)      Z     = (const float*)d_in[i];
        else if (in_sizes[i] == 6400000)  klist = (const int*)d_in[i];
        else                              rest[nrest++] = d_in[i];
    }
    const float* Wq   = (const float*)rest[0];
    const float* Wk   = (const float*)rest[1];
    const float* Wv   = (const float*)rest[2];
    const float* Wb   = (const float*)rest[3];
    const float* Wg   = (const float*)rest[4];
    const float* bg   = (const float*)rest[5];
    const float* Wout = (const float*)rest[6];
    const float* bout = (const float*)rest[7];
    float* out = (float*)d_out;

    const int smemA = (2 * 128 * SH + 4 * 128) * 2;                   // 70,656 B
    const int smemB = 320 * SH * 2 + 2048 * 4 + 2 * 128 * 4;          // 96,304 B

    cudaFuncSetAttribute(kproj_kv, cudaFuncAttributeMaxDynamicSharedMemorySize, smemA);
    cudaFuncSetAttribute(katt_out, cudaFuncAttributeMaxDynamicSharedMemorySize, smemB);

    kproj_kv<<<NBLKP, 256, smemA>>>(Z, Wk, Wv, Wb, klist);
    katt_out<<<NBLK, 256, smemB>>>(Z, Wq, Wg, bg, klist, Wout, bout, out);
}

// round 7
// speedup vs baseline: 4.3470x; 1.2145x over previous
#include <cuda_runtime.h>
#include <cuda_fp16.h>
#include <math.h>
#include <stdint.h>

// Problem constants
#define EN      200000
#define IND     128
#define HIDD    32
#define NH      4
#define OUTD    128
#define MAXK    16
#define TM      64                     // rows per block (attention kernel)
#define NBLK    (EN / TM)              // 3125
#define PTM     256                    // rows per tile (projection kernel)
#define PTILES  ((EN + PTM - 1) / PTM) // 782
#define PGRID   148
#define SH      136                    // smem row stride in halfs (128 + 8 pad)

// Scratch (device globals; no allocation)
__device__ __half g_kv[(size_t)EN * 256];  // [e][0:128]=k (head-major), [128:256]=v
__device__ __half g_q [(size_t)EN * 128];  // q, head-major
__device__ __half g_g [(size_t)EN * 128];  // sigmoid gate, head-major
__device__ float  g_bh[(size_t)EN * NH];   // [e][h]
__device__ int    g_kstride;               // 2 if klist is int64, 1 if int32

// m16n8k16 f16 MMA, fp32 accum. A row-major frag, B col-major frag.
__device__ __forceinline__ void mma16816(float c[4], unsigned a0, unsigned a1,
                                         unsigned a2, unsigned a3,
                                         unsigned b0, unsigned b1)
{
    asm volatile(
        "mma.sync.aligned.m16n8k16.row.col.f32.f16.f16.f32 "
        "{%0,%1,%2,%3}, {%4,%5,%6,%7}, {%8,%9}, {%0,%1,%2,%3};\n"
        : "+f"(c[0]), "+f"(c[1]), "+f"(c[2]), "+f"(c[3])
        : "r"(a0), "r"(a1), "r"(a2), "r"(a3), "r"(b0), "r"(b1));
}

__device__ __forceinline__ unsigned ldh2(const __half* p) { return *(const unsigned*)p; }

// ---------------------------------------------------------------------------
// Kernel A: ALL projections. 148 persistent blocks, 512 threads. All four
// weight matrices live in smem; 256-row Z tiles stream over them.
// chunk0=K, chunk1=V (-> g_kv), chunk2=Q (-> g_q), chunk3=G (sigmoid -> g_g).
// Plus per-row b = Z@Wb (-> g_bh) and klist width detection (block 0).
// ---------------------------------------------------------------------------
__global__ void __launch_bounds__(512, 1) kproj_all(
    const float* __restrict__ Z,
    const float* __restrict__ Wk,
    const float* __restrict__ Wv,
    const float* __restrict__ Wq,
    const float* __restrict__ Wg,
    const float* __restrict__ Wb,
    const float* __restrict__ bgv,
    const int*   __restrict__ kw)
{
    extern __shared__ __half sh[];
    __half* sZ  = sh;                        // [256][SH]
    __half* sW  = sh + PTM * SH;             // [4][128][SH]
    __half* sWb = sh + PTM * SH + 4 * 128 * SH;  // [512]
    float*  sbg = (float*)(sWb + 512);       // [128]

    const int tid = threadIdx.x;

    if (blockIdx.x == 0 && tid == 0) {
        int is64 = 1;
        for (int i = 0; i < 4096; i++) {
            int hi = kw[2 * i + 1];
            if (hi != 0 && hi != -1) { is64 = 0; break; }
        }
        g_kstride = is64 ? 2 : 1;
    }

    // Stage all weights once
    const float* Wsrcs[4] = {Wk, Wv, Wq, Wg};
    #pragma unroll
    for (int c = 0; c < 4; c++) {
        const float* Wsrc = Wsrcs[c];
        __half* dst = sW + c * 128 * SH;
        for (int i = tid; i < 128 * 32; i += 512) {
            int col = i >> 5, kq = i & 31;
            float4 w = *(const float4*)(Wsrc + (size_t)col * IND + kq * 4);
            *(__half2*)&dst[col * SH + kq * 4]     = __floats2half2_rn(w.x, w.y);
            *(__half2*)&dst[col * SH + kq * 4 + 2] = __floats2half2_rn(w.z, w.w);
        }
    }
    for (int i = tid; i < NH * IND; i += 512) sWb[i] = __float2half_rn(Wb[i]);
    for (int i = tid; i < 128; i += 512) sbg[i] = bgv[i];

    const int lane = tid & 31, wid = tid >> 5;
    const int g = lane >> 2, tig = lane & 3;
    const int rw = wid * 16;                  // 16 warps x 16 rows = 256 rows

    for (int t = blockIdx.x; t < PTILES; t += PGRID) {
        const int row0 = t * PTM;
        __syncthreads();   // previous tile fully consumed (incl. b tail & W staging on iter 0)

        // Load Z tile fp32 -> fp16
        for (int i = tid; i < PTM * 32; i += 512) {
            int r = i >> 5, c = i & 31;
            int rg = row0 + r; if (rg >= EN) rg = EN - 1;
            float4 v = *(const float4*)(Z + (size_t)rg * IND + c * 4);
            *(__half2*)&sZ[r * SH + c * 4]     = __floats2half2_rn(v.x, v.y);
            *(__half2*)&sZ[r * SH + c * 4 + 2] = __floats2half2_rn(v.z, v.w);
        }
        __syncthreads();

        const int r0g = row0 + rw + g;

        #pragma unroll
        for (int chunk = 0; chunk < 4; chunk++) {
            const __half* Wc = sW + chunk * 128 * SH;
            float acc[16][4] = {};
            #pragma unroll
            for (int k0 = 0; k0 < 8; k0++) {
                const __half* pa = sZ + (rw + g) * SH + k0 * 16 + tig * 2;
                unsigned a0 = ldh2(pa);
                unsigned a1 = ldh2(pa + 8 * SH);
                unsigned a2 = ldh2(pa + 8);
                unsigned a3 = ldh2(pa + 8 * SH + 8);
                #pragma unroll
                for (int nt = 0; nt < 16; nt++) {
                    const __half* pb = Wc + (nt * 8 + g) * SH + k0 * 16 + tig * 2;
                    mma16816(acc[nt], a0, a1, a2, a3, ldh2(pb), ldh2(pb + 8));
                }
            }

            if (chunk < 2) {
                #pragma unroll
                for (int nt = 0; nt < 16; nt++) {
                    int col = chunk * 128 + nt * 8 + tig * 2;
                    if (r0g < EN)
                        *(__half2*)&g_kv[(size_t)r0g * 256 + col] =
                            __floats2half2_rn(acc[nt][0], acc[nt][1]);
                    if (r0g + 8 < EN)
                        *(__half2*)&g_kv[(size_t)(r0g + 8) * 256 + col] =
                            __floats2half2_rn(acc[nt][2], acc[nt][3]);
                }
            } else if (chunk == 2) {
                #pragma unroll
                for (int nt = 0; nt < 16; nt++) {
                    int col = nt * 8 + tig * 2;
                    if (r0g < EN)
                        *(__half2*)&g_q[(size_t)r0g * 128 + col] =
                            __floats2half2_rn(acc[nt][0], acc[nt][1]);
                    if (r0g + 8 < EN)
                        *(__half2*)&g_q[(size_t)(r0g + 8) * 128 + col] =
                            __floats2half2_rn(acc[nt][2], acc[nt][3]);
                }
            } else {
                #pragma unroll
                for (int nt = 0; nt < 16; nt++) {
                    int col = nt * 8 + tig * 2;
                    float g0 = 1.f / (1.f + expf(-(acc[nt][0] + sbg[col])));
                    float g1 = 1.f / (1.f + expf(-(acc[nt][1] + sbg[col + 1])));
                    float g2 = 1.f / (1.f + expf(-(acc[nt][2] + sbg[col])));
                    float g3 = 1.f / (1.f + expf(-(acc[nt][3] + sbg[col + 1])));
                    if (r0g < EN)
                        *(__half2*)&g_g[(size_t)r0g * 128 + col] = __floats2half2_rn(g0, g1);
                    if (r0g + 8 < EN)
                        *(__half2*)&g_g[(size_t)(r0g + 8) * 128 + col] = __floats2half2_rn(g2, g3);
                }
            }
        }

        // b tail: 1024 (row, head) dots
        for (int tt = tid; tt < PTM * NH; tt += 512) {
            int r = tt >> 2, h = tt & 3;
            int rg = row0 + r;
            if (rg < EN) {
                float s = 0.f;
                #pragma unroll 8
                for (int k = 0; k < 128; k += 2) {
                    float2 a = __half22float2(*(__half2*)&sZ[r * SH + k]);
                    float2 b = __half22float2(*(__half2*)&sWb[h * IND + k]);
                    s += a.x * b.x + a.y * b.y;
                }
                g_bh[(size_t)rg * NH + h] = s;
            }
        }
    }
}

// ---------------------------------------------------------------------------
// Kernel B: gather attention (single-pass, no-max softmax) + gating +
// output GEMM. 64 rows per block, 256 threads, 3 CTAs/SM.
// ---------------------------------------------------------------------------
__global__ void __launch_bounds__(256, 3) katt_out(
    const int*   __restrict__ kw,
    const float* __restrict__ Wout,
    const float* __restrict__ bout,
    float*       __restrict__ out)
{
    extern __shared__ __half sh[];
    __half* sX  = sh;                          // [64][SH]  gated X (A operand)
    __half* sW  = sh + 64 * SH;                // [128][SH] Wout (B operand)
    int*    skl = (int*)(sh + 192 * SH);       // [64][32]
    float*  sbo = (float*)(skl + 2048);        // [128]

    const int tid  = threadIdx.x;
    const int row0 = blockIdx.x * TM;
    const int st   = g_kstride;

    // Stage Wout + bout + klist
    const float4* W4 = (const float4*)Wout;
    for (int i = tid; i < 128 * 32; i += 256) {
        int o = i >> 5, kq = i & 31;
        float4 w = W4[o * 32 + kq];
        *(__half2*)&sW[o * SH + kq * 4]     = __floats2half2_rn(w.x, w.y);
        *(__half2*)&sW[o * SH + kq * 4 + 2] = __floats2half2_rn(w.z, w.w);
    }
    for (int i = tid; i < 128; i += 256) sbo[i] = bout[i];
    for (int i = tid; i < TM * 32; i += 256)
        skl[i] = kw[((size_t)row0 * 32 + i) * st];
    __syncthreads();

    // ---- Gather phase: one thread per (row, head), single pass
    {
        const int r = tid >> 2, h = tid & 3;
        const size_t e = (size_t)row0 + r;

        float q[32];
        {
            const uint4* qp = (const uint4*)&g_q[e * 128 + h * 32];
            #pragma unroll
            for (int c = 0; c < 4; c++) {
                uint4 u = qp[c];
                const __half2* hp = (const __half2*)&u;
                #pragma unroll
                for (int p = 0; p < 4; p++) {
                    float2 f = __half22float2(hp[p]);
                    q[c*8 + p*2] = f.x; q[c*8 + p*2 + 1] = f.y;
                }
            }
        }

        const float scale = 0.17677669529663687f;   // 1/sqrt(32)
        float den = 0.f;
        float att[32];
        #pragma unroll
        for (int j = 0; j < 32; j++) att[j] = 0.f;

        #pragma unroll
        for (int s = 0; s < MAXK; s++) {
            int ii = skl[r * 32 + s];
            if (ii >= 0) {
                ii = min(ii, EN - 1);
                const uint4* kp = (const uint4*)&g_kv[(size_t)ii * 256 + h * 32];
                float d = 0.f;
                #pragma unroll
                for (int c = 0; c < 4; c++) {
                    uint4 u = kp[c];
                    const __half2* hp = (const __half2*)&u;
                    #pragma unroll
                    for (int p = 0; p < 4; p++) {
                        float2 f = __half22float2(hp[p]);
                        d += q[c*8 + p*2] * f.x + q[c*8 + p*2 + 1] * f.y;
                    }
                }
                int jj = skl[r * 32 + 16 + s];
                jj = min(max(jj, 0), EN - 1);
                float w = expf(scale * d + g_bh[(size_t)jj * NH + h]);
                den += w;
                const uint4* vp = (const uint4*)&g_kv[(size_t)ii * 256 + 128 + h * 32];
                #pragma unroll
                for (int c = 0; c < 4; c++) {
                    uint4 u = vp[c];
                    const __half2* hp = (const __half2*)&u;
                    #pragma unroll
                    for (int p = 0; p < 4; p++) {
                        float2 f = __half22float2(hp[p]);
                        att[c*8 + p*2]     += w * f.x;
                        att[c*8 + p*2 + 1] += w * f.y;
                    }
                }
            } else {
                den += 1.f;   // exp(0): matches reference's masked score of 0
            }
        }

        // gate and write X (A operand for out GEMM)
        const float inv = 1.f / den;
        const uint4* gp = (const uint4*)&g_g[e * 128 + h * 32];
        #pragma unroll
        for (int c = 0; c < 4; c++) {
            uint4 u = gp[c];
            const __half2* hp = (const __half2*)&u;
            #pragma unroll
            for (int p = 0; p < 4; p++) {
                float2 gf = __half22float2(hp[p]);
                *(__half2*)&sX[r * SH + h * 32 + c * 8 + p * 2] =
                    __floats2half2_rn(gf.x * att[c*8 + p*2] * inv,
                                      gf.y * att[c*8 + p*2 + 1] * inv);
            }
        }
    }
    __syncthreads();

    // ---- Output GEMM: out = X @ Wout^T + bout. 8 warps: 4m x 2n.
    const int lane = tid & 31, wid = tid >> 5;
    const int g = lane >> 2, tig = lane & 3;
    const int rw = (wid & 3) * 16;
    const int cw = (wid >> 2) * 64;

    float acc[8][4] = {};
    #pragma unroll
    for (int k0 = 0; k0 < 8; k0++) {
        const __half* pa = sX + (rw + g) * SH + k0 * 16 + tig * 2;
        unsigned a0 = ldh2(pa);
        unsigned a1 = ldh2(pa + 8 * SH);
        unsigned a2 = ldh2(pa + 8);
        unsigned a3 = ldh2(pa + 8 * SH + 8);
        #pragma unroll
        for (int nt = 0; nt < 8; nt++) {
            const __half* pb = sW + (cw + nt * 8 + g) * SH + k0 * 16 + tig * 2;
            mma16816(acc[nt], a0, a1, a2, a3, ldh2(pb), ldh2(pb + 8));
        }
    }

    #pragma unroll
    for (int nt = 0; nt < 8; nt++) {
        int col = cw + nt * 8 + tig * 2;
        size_t e0 = (size_t)(row0 + rw + g);
        float2 o0 = make_float2(acc[nt][0] + sbo[col], acc[nt][1] + sbo[col + 1]);
        float2 o1 = make_float2(acc[nt][2] + sbo[col], acc[nt][3] + sbo[col + 1]);
        *(float2*)&out[e0 * 128 + col]       = o0;
        *(float2*)&out[(e0 + 8) * 128 + col] = o1;
    }
}

// ---------------------------------------------------------------------------
extern "C" void kernel_launch(void* const* d_in, const int* in_sizes, int n_in,
                              void* d_out, int out_size)
{
    // Locate Z and klist by element count; remaining inputs keep dict order:
    // Wq, Wk, Wv, Wb, Wg, bg, Wout, bout
    const float* Z = nullptr;
    const int*   klist = nullptr;
    const void*  rest[16];
    int nrest = 0;
    for (int i = 0; i < n_in; i++) {
        if (in_sizes[i] == 25600000)      Z     = (const float*)d_in[i];
        else if (in_sizes[i] == 6400000)  klist = (const int*)d_in[i];
        else                              rest[nrest++] = d_in[i];
    }
    const float* Wq   = (const float*)rest[0];
    const float* Wk   = (const float*)rest[1];
    const float* Wv   = (const float*)rest[2];
    const float* Wb   = (const float*)rest[3];
    const float* Wg   = (const float*)rest[4];
    const float* bg   = (const float*)rest[5];
    const float* Wout = (const float*)rest[6];
    const float* bout = (const float*)rest[7];
    float* out = (float*)d_out;

    const int smemP = (PTM * SH + 4 * 128 * SH + 512) * 2 + 128 * 4;  // 210,432 B
    const int smemB = 192 * SH * 2 + 2048 * 4 + 128 * 4;              // 60,928 B

    cudaFuncSetAttribute(kproj_all, cudaFuncAttributeMaxDynamicSharedMemorySize, smemP);
    cudaFuncSetAttribute(katt_out,  cudaFuncAttributeMaxDynamicSharedMemorySize, smemB);

    kproj_all<<<PGRID, 512, smemP>>>(Z, Wk, Wv, Wq, Wg, Wb, bg, klist);
    katt_out <<<NBLK, 256, smemB>>>(klist, Wout, bout, out);
}

// round 9
// speedup vs baseline: 5.0149x; 1.1536x over previous
#include <cuda_runtime.h>
#include <cuda_fp16.h>
#include <math.h>
#include <stdint.h>

// Problem constants
#define EN      200000
#define IND     128
#define HIDD    32
#define NH      4
#define OUTD    128
#define MAXK    16
#define TM      64                     // rows per block (attention kernel)
#define NBLK    (EN / TM)              // 3125
#define PTM     256                    // rows per tile (projection kernel)
#define PTILES  ((EN + PTM - 1) / PTM) // 782
#define PGRID   148
#define SH      136                    // smem row stride in halfs (128 + 8 pad)

// Scratch (device globals; no allocation)
__device__ __half g_kv[(size_t)EN * 256];  // [e][0:128]=k (head-major), [128:256]=v
__device__ __half g_q [(size_t)EN * 128];  // q, head-major
__device__ __half g_g [(size_t)EN * 128];  // sigmoid gate, head-major
__device__ float  g_bh[(size_t)EN * NH];   // [e][h]
__device__ int    g_kstride;               // 2 if klist is int64, 1 if int32

// m16n8k16 f16 MMA, fp32 accum. A row-major frag, B col-major frag.
__device__ __forceinline__ void mma16816(float c[4], unsigned a0, unsigned a1,
                                         unsigned a2, unsigned a3,
                                         unsigned b0, unsigned b1)
{
    asm volatile(
        "mma.sync.aligned.m16n8k16.row.col.f32.f16.f16.f32 "
        "{%0,%1,%2,%3}, {%4,%5,%6,%7}, {%8,%9}, {%0,%1,%2,%3};\n"
        : "+f"(c[0]), "+f"(c[1]), "+f"(c[2]), "+f"(c[3])
        : "r"(a0), "r"(a1), "r"(a2), "r"(a3), "r"(b0), "r"(b1));
}

__device__ __forceinline__ unsigned ldh2(const __half* p) { return *(const unsigned*)p; }

// ---------------------------------------------------------------------------
// Kernel A: ALL projections. 148 persistent blocks, 512 threads. All four
// weight matrices live in smem; 256-row Z tiles stream over them.
// chunk0=K, chunk1=V (-> g_kv), chunk2=Q (-> g_q), chunk3=G (sigmoid -> g_g).
// Plus per-row b = Z@Wb (-> g_bh) and klist width detection (block 0).
// ---------------------------------------------------------------------------
__global__ void __launch_bounds__(512, 1) kproj_all(
    const float* __restrict__ Z,
    const float* __restrict__ Wk,
    const float* __restrict__ Wv,
    const float* __restrict__ Wq,
    const float* __restrict__ Wg,
    const float* __restrict__ Wb,
    const float* __restrict__ bgv,
    const int*   __restrict__ kw)
{
    extern __shared__ __half sh[];
    __half* sZ  = sh;                        // [256][SH]
    __half* sW  = sh + PTM * SH;             // [4][128][SH]
    __half* sWb = sh + PTM * SH + 4 * 128 * SH;  // [512]
    float*  sbg = (float*)(sWb + 512);       // [128]

    const int tid = threadIdx.x;

    if (blockIdx.x == 0 && tid == 0) {
        int is64 = 1;
        for (int i = 0; i < 4096; i++) {
            int hi = kw[2 * i + 1];
            if (hi != 0 && hi != -1) { is64 = 0; break; }
        }
        g_kstride = is64 ? 2 : 1;
    }

    // Stage all weights once
    const float* Wsrcs[4] = {Wk, Wv, Wq, Wg};
    #pragma unroll
    for (int c = 0; c < 4; c++) {
        const float* Wsrc = Wsrcs[c];
        __half* dst = sW + c * 128 * SH;
        for (int i = tid; i < 128 * 32; i += 512) {
            int col = i >> 5, kq = i & 31;
            float4 w = *(const float4*)(Wsrc + (size_t)col * IND + kq * 4);
            *(__half2*)&dst[col * SH + kq * 4]     = __floats2half2_rn(w.x, w.y);
            *(__half2*)&dst[col * SH + kq * 4 + 2] = __floats2half2_rn(w.z, w.w);
        }
    }
    for (int i = tid; i < NH * IND; i += 512) sWb[i] = __float2half_rn(Wb[i]);
    for (int i = tid; i < 128; i += 512) sbg[i] = bgv[i];

    const int lane = tid & 31, wid = tid >> 5;
    const int g = lane >> 2, tig = lane & 3;
    const int rw = wid * 16;                  // 16 warps x 16 rows = 256 rows

    for (int t = blockIdx.x; t < PTILES; t += PGRID) {
        const int row0 = t * PTM;
        __syncthreads();   // previous tile fully consumed

        // Load Z tile fp32 -> fp16
        for (int i = tid; i < PTM * 32; i += 512) {
            int r = i >> 5, c = i & 31;
            int rg = row0 + r; if (rg >= EN) rg = EN - 1;
            float4 v = *(const float4*)(Z + (size_t)rg * IND + c * 4);
            *(__half2*)&sZ[r * SH + c * 4]     = __floats2half2_rn(v.x, v.y);
            *(__half2*)&sZ[r * SH + c * 4 + 2] = __floats2half2_rn(v.z, v.w);
        }
        __syncthreads();

        const int r0g = row0 + rw + g;

        #pragma unroll
        for (int chunk = 0; chunk < 4; chunk++) {
            const __half* Wc = sW + chunk * 128 * SH;
            float acc[16][4] = {};
            #pragma unroll
            for (int k0 = 0; k0 < 8; k0++) {
                const __half* pa = sZ + (rw + g) * SH + k0 * 16 + tig * 2;
                unsigned a0 = ldh2(pa);
                unsigned a1 = ldh2(pa + 8 * SH);
                unsigned a2 = ldh2(pa + 8);
                unsigned a3 = ldh2(pa + 8 * SH + 8);
                #pragma unroll
                for (int nt = 0; nt < 16; nt++) {
                    const __half* pb = Wc + (nt * 8 + g) * SH + k0 * 16 + tig * 2;
                    mma16816(acc[nt], a0, a1, a2, a3, ldh2(pb), ldh2(pb + 8));
                }
            }

            if (chunk < 2) {
                #pragma unroll
                for (int nt = 0; nt < 16; nt++) {
                    int col = chunk * 128 + nt * 8 + tig * 2;
                    if (r0g < EN)
                        *(__half2*)&g_kv[(size_t)r0g * 256 + col] =
                            __floats2half2_rn(acc[nt][0], acc[nt][1]);
                    if (r0g + 8 < EN)
                        *(__half2*)&g_kv[(size_t)(r0g + 8) * 256 + col] =
                            __floats2half2_rn(acc[nt][2], acc[nt][3]);
                }
            } else if (chunk == 2) {
                #pragma unroll
                for (int nt = 0; nt < 16; nt++) {
                    int col = nt * 8 + tig * 2;
                    if (r0g < EN)
                        *(__half2*)&g_q[(size_t)r0g * 128 + col] =
                            __floats2half2_rn(acc[nt][0], acc[nt][1]);
                    if (r0g + 8 < EN)
                        *(__half2*)&g_q[(size_t)(r0g + 8) * 128 + col] =
                            __floats2half2_rn(acc[nt][2], acc[nt][3]);
                }
            } else {
                #pragma unroll
                for (int nt = 0; nt < 16; nt++) {
                    int col = nt * 8 + tig * 2;
                    float g0 = 1.f / (1.f + __expf(-(acc[nt][0] + sbg[col])));
                    float g1 = 1.f / (1.f + __expf(-(acc[nt][1] + sbg[col + 1])));
                    float g2 = 1.f / (1.f + __expf(-(acc[nt][2] + sbg[col])));
                    float g3 = 1.f / (1.f + __expf(-(acc[nt][3] + sbg[col + 1])));
                    if (r0g < EN)
                        *(__half2*)&g_g[(size_t)r0g * 128 + col] = __floats2half2_rn(g0, g1);
                    if (r0g + 8 < EN)
                        *(__half2*)&g_g[(size_t)(r0g + 8) * 128 + col] = __floats2half2_rn(g2, g3);
                }
            }
        }

        // b tail: 1024 (row, head) dots
        for (int tt = tid; tt < PTM * NH; tt += 512) {
            int r = tt >> 2, h = tt & 3;
            int rg = row0 + r;
            if (rg < EN) {
                float s = 0.f;
                #pragma unroll 8
                for (int k = 0; k < 128; k += 2) {
                    float2 a = __half22float2(*(__half2*)&sZ[r * SH + k]);
                    float2 b = __half22float2(*(__half2*)&sWb[h * IND + k]);
                    s += a.x * b.x + a.y * b.y;
                }
                g_bh[(size_t)rg * NH + h] = s;
            }
        }
    }
}

// ---------------------------------------------------------------------------
// Kernel B: gather attention + gating + output GEMM. 512 threads, 64 rows.
// A thread PAIR handles one (row, head): p = tid&1 selects 16-dim half.
// Slot loop is BRANCH-FREE (invalid slots load row 0, weight 0) so the
// full-mask pair shuffle never sees divergent lanes.
// ---------------------------------------------------------------------------
__global__ void __launch_bounds__(512, 2) katt_out(
    const int*   __restrict__ kw,
    const float* __restrict__ Wout,
    const float* __restrict__ bout,
    float*       __restrict__ out)
{
    extern __shared__ __half sh[];
    __half* sX  = sh;                          // [64][SH]  gated X (A operand)
    __half* sW  = sh + 64 * SH;                // [128][SH] Wout (B operand)
    int*    skl = (int*)(sh + 192 * SH);       // [64][32]
    float*  sbo = (float*)(skl + 2048);        // [128]

    const int tid  = threadIdx.x;
    const int row0 = blockIdx.x * TM;
    const int st   = g_kstride;

    // Stage Wout + bout + klist
    const float4* W4 = (const float4*)Wout;
    for (int i = tid; i < 128 * 32; i += 512) {
        int o = i >> 5, kq = i & 31;
        float4 w = W4[o * 32 + kq];
        *(__half2*)&sW[o * SH + kq * 4]     = __floats2half2_rn(w.x, w.y);
        *(__half2*)&sW[o * SH + kq * 4 + 2] = __floats2half2_rn(w.z, w.w);
    }
    for (int i = tid; i < 128; i += 512) sbo[i] = bout[i];
    for (int i = tid; i < TM * 32; i += 512)
        skl[i] = kw[((size_t)row0 * 32 + i) * st];
    __syncthreads();

    // ---- Gather phase: thread pair per (row, head), branch-free slots
    {
        const int p = tid & 1;            // 16-dim half selector
        const int h = (tid >> 1) & 3;     // head
        const int r = tid >> 3;           // row in tile
        const size_t e = (size_t)row0 + r;
        const int off = h * 32 + p * 16;  // offset into 128-wide head-major vec

        float q[16];
        {
            const uint4* qp = (const uint4*)&g_q[e * 128 + off];
            #pragma unroll
            for (int c = 0; c < 2; c++) {
                uint4 u = qp[c];
                const __half2* hp = (const __half2*)&u;
                #pragma unroll
                for (int pp = 0; pp < 4; pp++) {
                    float2 f = __half22float2(hp[pp]);
                    q[c*8 + pp*2] = f.x; q[c*8 + pp*2 + 1] = f.y;
                }
            }
        }

        const float scale = 0.17677669529663687f;   // 1/sqrt(32)
        float den = 0.f;
        float att[16];
        #pragma unroll
        for (int j = 0; j < 16; j++) att[j] = 0.f;

        #pragma unroll
        for (int s = 0; s < MAXK; s++) {
            int ii_raw = skl[r * 32 + s];
            bool valid = (ii_raw >= 0);
            int ii = valid ? min(ii_raw, EN - 1) : 0;
            int jj = skl[r * 32 + 16 + s];
            jj = min(max(jj, 0), EN - 1);

            const uint4* kp = (const uint4*)&g_kv[(size_t)ii * 256 + off];
            float d = 0.f;
            #pragma unroll
            for (int c = 0; c < 2; c++) {
                uint4 u = kp[c];
                const __half2* hp = (const __half2*)&u;
                #pragma unroll
                for (int pp = 0; pp < 4; pp++) {
                    float2 f = __half22float2(hp[pp]);
                    d += q[c*8 + pp*2] * f.x + q[c*8 + pp*2 + 1] * f.y;
                }
            }
            d += __shfl_xor_sync(0xFFFFFFFF, d, 1);   // pair reduction (converged)

            float w = valid ? __expf(scale * d + g_bh[(size_t)jj * NH + h]) : 0.f;
            den += valid ? w : 1.f;                   // exp(0) for masked slot

            const uint4* vp = (const uint4*)&g_kv[(size_t)ii * 256 + 128 + off];
            #pragma unroll
            for (int c = 0; c < 2; c++) {
                uint4 u = vp[c];
                const __half2* hp = (const __half2*)&u;
                #pragma unroll
                for (int pp = 0; pp < 4; pp++) {
                    float2 f = __half22float2(hp[pp]);
                    att[c*8 + pp*2]     += w * f.x;
                    att[c*8 + pp*2 + 1] += w * f.y;
                }
            }
        }

        // gate and write X (A operand for out GEMM)
        const float inv = 1.f / den;
        const uint4* gp = (const uint4*)&g_g[e * 128 + off];
        #pragma unroll
        for (int c = 0; c < 2; c++) {
            uint4 u = gp[c];
            const __half2* hp = (const __half2*)&u;
            #pragma unroll
            for (int pp = 0; pp < 4; pp++) {
                float2 gf = __half22float2(hp[pp]);
                *(__half2*)&sX[r * SH + off + c * 8 + pp * 2] =
                    __floats2half2_rn(gf.x * att[c*8 + pp*2] * inv,
                                      gf.y * att[c*8 + pp*2 + 1] * inv);
            }
        }
    }
    __syncthreads();

    // ---- Output GEMM: out = X @ Wout^T + bout. 16 warps: 4m x 4n.
    const int lane = tid & 31, wid = tid >> 5;
    const int g = lane >> 2, tig = lane & 3;
    const int rw = (wid & 3) * 16;      // row band
    const int cw = (wid >> 2) * 32;     // col band

    float acc[4][4] = {};
    #pragma unroll
    for (int k0 = 0; k0 < 8; k0++) {
        const __half* pa = sX + (rw + g) * SH + k0 * 16 + tig * 2;
        unsigned a0 = ldh2(pa);
        unsigned a1 = ldh2(pa + 8 * SH);
        unsigned a2 = ldh2(pa + 8);
        unsigned a3 = ldh2(pa + 8 * SH + 8);
        #pragma unroll
        for (int nt = 0; nt < 4; nt++) {
            const __half* pb = sW + (cw + nt * 8 + g) * SH + k0 * 16 + tig * 2;
            mma16816(acc[nt], a0, a1, a2, a3, ldh2(pb), ldh2(pb + 8));
        }
    }

    #pragma unroll
    for (int nt = 0; nt < 4; nt++) {
        int col = cw + nt * 8 + tig * 2;
        size_t e0 = (size_t)(row0 + rw + g);
        float2 o0 = make_float2(acc[nt][0] + sbo[col], acc[nt][1] + sbo[col + 1]);
        float2 o1 = make_float2(acc[nt][2] + sbo[col], acc[nt][3] + sbo[col + 1]);
        *(float2*)&out[e0 * 128 + col]       = o0;
        *(float2*)&out[(e0 + 8) * 128 + col] = o1;
    }
}

// ---------------------------------------------------------------------------
extern "C" void kernel_launch(void* const* d_in, const int* in_sizes, int n_in,
                              void* d_out, int out_size)
{
    // Locate Z and klist by element count; remaining inputs keep dict order:
    // Wq, Wk, Wv, Wb, Wg, bg, Wout, bout
    const float* Z = nullptr;
    const int*   klist = nullptr;
    const void*  rest[16];
    int nrest = 0;
    for (int i = 0; i < n_in; i++) {
        if (in_sizes[i] == 25600000)      Z     = (const float*)d_in[i];
        else if (in_sizes[i] == 6400000)  klist = (const int*)d_in[i];
        else                              rest[nrest++] = d_in[i];
    }
    const float* Wq   = (const float*)rest[0];
    const float* Wk   = (const float*)rest[1];
    const float* Wv   = (const float*)rest[2];
    const float* Wb   = (const float*)rest[3];
    const float* Wg   = (const float*)rest[4];
    const float* bg   = (const float*)rest[5];
    const float* Wout = (const float*)rest[6];
    const float* bout = (const float*)rest[7];
    float* out = (float*)d_out;

    const int smemP = (PTM * SH + 4 * 128 * SH + 512) * 2 + 128 * 4;  // 210,432 B
    const int smemB = 192 * SH * 2 + 2048 * 4 + 128 * 4;              // 60,928 B

    cudaFuncSetAttribute(kproj_all, cudaFuncAttributeMaxDynamicSharedMemorySize, smemP);
    cudaFuncSetAttribute(katt_out,  cudaFuncAttributeMaxDynamicSharedMemorySize, smemB);

    kproj_all<<<PGRID, 512, smemP>>>(Z, Wk, Wv, Wq, Wg, Wb, bg, klist);
    katt_out <<<NBLK, 512, smemB>>>(klist, Wout, bout, out);
}